// round 1
// baseline (speedup 1.0000x reference)
#include <cuda_runtime.h>
#include <cstdint>

// Problem dims (fixed by the dataset)
#define BDIM 256
#define TDIM 500
#define IDIM 1024
#define ODIM 2048

#define M_GEMM (BDIM * TDIM)   // 128000
#define N_GEMM ODIM            // 2048
#define K_GEMM IDIM            // 1024

// GEMM tiling
#define BM 128
#define BN 128
#define BK 16
#define TM 8
#define TN 8

// Scratch for h = x @ w : [B*T, O] fp32 = 1.05 GB (device global, no runtime alloc)
__device__ float g_h[(size_t)M_GEMM * N_GEMM];

// ---------------------------------------------------------------------------
// Kernel 1: h = x @ w   (fp32 SIMT tiled GEMM, 128x128x16, 8x8 microtiles)
// ---------------------------------------------------------------------------
__global__ void __launch_bounds__(256, 2)
gemm_kernel(const float* __restrict__ A,   // [M, K] row-major (x reshaped)
            const float* __restrict__ B)   // [K, N] row-major (w)
{
    __shared__ float As[BK][BM + 4];  // transposed A tile (+pad for banked stores)
    __shared__ float Bs[BK][BN];

    const int tid = threadIdx.x;            // 0..255
    const int ty  = tid >> 4;               // 0..15 (m micro-row)
    const int tx  = tid & 15;               // 0..15 (n micro-col)

    const int block_m = blockIdx.y * BM;
    const int block_n = blockIdx.x * BN;

    const float* Aptr = A + (size_t)block_m * K_GEMM;
    const float* Bptr = B + block_n;

    float acc[TM][TN];
#pragma unroll
    for (int i = 0; i < TM; i++)
#pragma unroll
        for (int j = 0; j < TN; j++) acc[i][j] = 0.0f;

    for (int k0 = 0; k0 < K_GEMM; k0 += BK) {
        // --- load A tile: 128 rows x 16 cols = 512 float4, 2 per thread ---
#pragma unroll
        for (int i = 0; i < 2; i++) {
            int f = tid + i * 256;          // float4 index 0..511
            int r = f >> 2;                 // row within tile 0..127
            int c = (f & 3) << 2;           // col within tile {0,4,8,12}
            float4 v = *(const float4*)(Aptr + (size_t)r * K_GEMM + k0 + c);
            As[c + 0][r] = v.x;
            As[c + 1][r] = v.y;
            As[c + 2][r] = v.z;
            As[c + 3][r] = v.w;
        }
        // --- load B tile: 16 rows x 128 cols = 512 float4, 2 per thread ---
#pragma unroll
        for (int i = 0; i < 2; i++) {
            int f = tid + i * 256;
            int r = f >> 5;                 // row (k) 0..15
            int c = (f & 31) << 2;          // col 0..124 step 4
            *(float4*)(&Bs[r][c]) =
                *(const float4*)(Bptr + (size_t)(k0 + r) * N_GEMM + c);
        }
        __syncthreads();

#pragma unroll
        for (int kk = 0; kk < BK; kk++) {
            float a[TM], b[TN];
#pragma unroll
            for (int i = 0; i < TM; i++) a[i] = As[kk][ty * TM + i];
#pragma unroll
            for (int j = 0; j < TN; j++) b[j] = Bs[kk][tx * TN + j];
#pragma unroll
            for (int i = 0; i < TM; i++)
#pragma unroll
                for (int j = 0; j < TN; j++)
                    acc[i][j] = fmaf(a[i], b[j], acc[i][j]);
        }
        __syncthreads();
    }

    // --- write h tile (float4) ---
    float* Cp = g_h + (size_t)block_m * N_GEMM + block_n;
#pragma unroll
    for (int i = 0; i < TM; i++) {
        int r = ty * TM + i;
#pragma unroll
        for (int j = 0; j < TN; j += 4) {
            float4 v = make_float4(acc[i][j], acc[i][j + 1],
                                   acc[i][j + 2], acc[i][j + 3]);
            *(float4*)(Cp + (size_t)r * N_GEMM + tx * TN + j) = v;
        }
    }
}

// ---------------------------------------------------------------------------
// Kernel 2: syn[b,0,:] = 0 ; syn[b,t,:] = decay * syn[b,t-1,:] + h[b,t-1,:]
// One thread per (b, 4 consecutive o). Coalesced across o within each warp.
// ---------------------------------------------------------------------------
__global__ void __launch_bounds__(256)
scan_kernel(const float* __restrict__ alpha,   // [O]
            const float* __restrict__ beta,    // [O]
            float* __restrict__ out)           // [B, T, O]
{
    const int idx = blockIdx.x * blockDim.x + threadIdx.x;  // 0 .. B*O/4-1
    const int b  = idx >> 9;            // O/4 = 512 quads per batch
    const int oq = idx & 511;
    const int o  = oq << 2;

    float4 a4 = *(const float4*)(alpha + o);
    float4 b4 = *(const float4*)(beta + o);
    float4 d;
    d.x = a4.x * (1.0f - b4.x);
    d.y = a4.y * (1.0f - b4.y);
    d.z = a4.z * (1.0f - b4.z);
    d.w = a4.w * (1.0f - b4.w);

    const float4* hp = (const float4*)(g_h + (size_t)b * TDIM * ODIM + o);
    float4*       op = (float4*)(out  + (size_t)b * TDIM * ODIM + o);
    const int stride4 = ODIM / 4;  // 512 float4 between consecutive t

    float4 syn = make_float4(0.f, 0.f, 0.f, 0.f);
    op[0] = syn;  // t = 0 is all zeros (output buffer is poisoned, must write)

#pragma unroll 4
    for (int t = 1; t < TDIM; t++) {
        float4 h = hp[(size_t)(t - 1) * stride4];
        syn.x = fmaf(d.x, syn.x, h.x);
        syn.y = fmaf(d.y, syn.y, h.y);
        syn.z = fmaf(d.z, syn.z, h.z);
        syn.w = fmaf(d.w, syn.w, h.w);
        op[(size_t)t * stride4] = syn;
    }
}

// ---------------------------------------------------------------------------
extern "C" void kernel_launch(void* const* d_in, const int* in_sizes, int n_in,
                              void* d_out, int out_size)
{
    const float* x     = (const float*)d_in[0];  // [B, T, I]
    const float* w     = (const float*)d_in[1];  // [I, O]
    const float* alpha = (const float*)d_in[2];  // [1, O]
    const float* beta  = (const float*)d_in[3];  // [1, O]
    float* out         = (float*)d_out;          // [B, T, O]

    dim3 ggrid(N_GEMM / BN, M_GEMM / BM);        // (16, 1000)
    gemm_kernel<<<ggrid, 256>>>(x, w);

    const int scan_threads = BDIM * (ODIM / 4);  // 131072
    scan_kernel<<<scan_threads / 256, 256>>>(alpha, beta, out);
}

// round 4
// speedup vs baseline: 5.6018x; 5.6018x over previous
#include <cuda_runtime.h>
#include <cuda_fp16.h>
#include <cstdint>

// Problem dims (fixed)
#define BDIM 256
#define TDIM 500
#define IDIM 1024
#define ODIM 2048
#define M_GEMM (BDIM * TDIM)   // 128000
#define N_GEMM ODIM            // 2048
#define K_GEMM IDIM            // 1024

// GEMM tiling
#define BM 128
#define BN 128
#define BK 32
#define STAGES 4
#define NCHUNK (K_GEMM / BK)   // 32

// Padded smem strides (bytes) -> conflict-free ldmatrix (8 rows hit 8 distinct
// 16B bank-groups: A stride 80B = 5 chunks, gcd(5,8)=1; B stride 272B = 17 chunks)
#define A_STRIDE 80            // 32 halves (64B) + 16B pad
#define B_STRIDE 272           // 128 halves (256B) + 16B pad
#define A_STAGE_BYTES (128 * A_STRIDE)   // 10240
#define B_STAGE_BYTES (32 * B_STRIDE)    // 8704
#define STAGE_BYTES (A_STAGE_BYTES + B_STAGE_BYTES)  // 18944 (128B multiple)
#define SMEM_TOTAL (STAGES * STAGE_BYTES)            // 75776

// Device scratch (no runtime allocation allowed)
__device__ __align__(1024) float  g_h [(size_t)M_GEMM * N_GEMM];  // 1.05 GB
__device__ __align__(1024) __half g_xh[(size_t)M_GEMM * K_GEMM];  // 256 MB
__device__ __align__(1024) __half g_wh[(size_t)K_GEMM * N_GEMM];  // 4 MB

// ---------------------------------------------------------------------------
__device__ __forceinline__ uint32_t smem_u32(const void* p) {
    uint32_t a;
    asm("{ .reg .u64 t; cvta.to.shared.u64 t, %1; cvt.u32.u64 %0, t; }" : "=r"(a) : "l"(p));
    return a;
}
__device__ __forceinline__ void cp16(uint32_t dst, const void* src) {
    asm volatile("cp.async.cg.shared.global [%0], [%1], 16;" :: "r"(dst), "l"(src));
}
#define CP_COMMIT() asm volatile("cp.async.commit_group;" ::: "memory")

__device__ __forceinline__ void ldsm_x4(uint32_t* r, uint32_t addr) {
    asm volatile("ldmatrix.sync.aligned.m8n8.x4.shared.b16 {%0,%1,%2,%3}, [%4];"
                 : "=r"(r[0]), "=r"(r[1]), "=r"(r[2]), "=r"(r[3]) : "r"(addr));
}
__device__ __forceinline__ void ldsm_x4_t(uint32_t* r, uint32_t addr) {
    asm volatile("ldmatrix.sync.aligned.m8n8.x4.trans.shared.b16 {%0,%1,%2,%3}, [%4];"
                 : "=r"(r[0]), "=r"(r[1]), "=r"(r[2]), "=r"(r[3]) : "r"(addr));
}
__device__ __forceinline__ void mma16816(float* c, const uint32_t* a, uint32_t b0, uint32_t b1) {
    asm volatile(
        "mma.sync.aligned.m16n8k16.row.col.f32.f16.f16.f32 "
        "{%0,%1,%2,%3}, {%4,%5,%6,%7}, {%8,%9}, {%0,%1,%2,%3};"
        : "+f"(c[0]), "+f"(c[1]), "+f"(c[2]), "+f"(c[3])
        : "r"(a[0]), "r"(a[1]), "r"(a[2]), "r"(a[3]), "r"(b0), "r"(b1));
}

// ---------------------------------------------------------------------------
// Pre-pass: fp32 -> fp16 conversions
// ---------------------------------------------------------------------------
__global__ void cvt_x_kernel(const float* __restrict__ x) {
    const size_t total4 = (size_t)M_GEMM * K_GEMM / 4;
    size_t stride = (size_t)gridDim.x * blockDim.x;
    for (size_t i = (size_t)blockIdx.x * blockDim.x + threadIdx.x; i < total4; i += stride) {
        float4 v = ((const float4*)x)[i];
        __half2* dst = (__half2*)(g_xh + i * 4);
        dst[0] = __floats2half2_rn(v.x, v.y);
        dst[1] = __floats2half2_rn(v.z, v.w);
    }
}
__global__ void cvt_w_kernel(const float* __restrict__ w) {
    const size_t total4 = (size_t)K_GEMM * N_GEMM / 4;
    size_t stride = (size_t)gridDim.x * blockDim.x;
    for (size_t i = (size_t)blockIdx.x * blockDim.x + threadIdx.x; i < total4; i += stride) {
        float4 v = ((const float4*)w)[i];
        __half2* dst = (__half2*)(g_wh + i * 4);
        dst[0] = __floats2half2_rn(v.x, v.y);
        dst[1] = __floats2half2_rn(v.z, v.w);
    }
}

// ---------------------------------------------------------------------------
// HMMA GEMM: h[M,N] = xh[M,K] * wh[K,N]
// ---------------------------------------------------------------------------
__device__ __forceinline__ void issue_loads(int tid, int chunk, int block_m, int block_n,
                                            uint32_t smem_base) {
    const int k0 = chunk * BK;
    const uint32_t sb = smem_base + (chunk & (STAGES - 1)) * STAGE_BYTES;
    // A tile: 128 rows x 64B = 512 chunks of 16B
#pragma unroll
    for (int i = 0; i < 2; i++) {
        int idx = tid + i * 256;
        int r = idx >> 2, q = idx & 3;
        cp16(sb + r * A_STRIDE + q * 16,
             g_xh + (size_t)(block_m + r) * K_GEMM + k0 + q * 8);
    }
    // B tile: 32 rows x 256B = 512 chunks of 16B
#pragma unroll
    for (int i = 0; i < 2; i++) {
        int idx = tid + i * 256;
        int r = idx >> 4, q = idx & 15;
        cp16(sb + A_STAGE_BYTES + r * B_STRIDE + q * 16,
             g_wh + (size_t)(k0 + r) * N_GEMM + block_n + q * 8);
    }
    CP_COMMIT();
}

__global__ void __launch_bounds__(256, 2)
gemm_hmma_kernel() {
    extern __shared__ char smem[];
    const uint32_t sbase = smem_u32(smem);
    const int tid  = threadIdx.x;
    const int wid  = tid >> 5;
    const int lane = tid & 31;
    const int wm = wid >> 1;          // 0..3  (32-row slab)
    const int wn = wid & 1;           // 0..1  (64-col slab)
    const int block_m = blockIdx.y * BM;
    const int block_n = blockIdx.x * BN;

    float c[2][8][4] = {};

    // Prologue: chunks 0..STAGES-2
#pragma unroll
    for (int p = 0; p < STAGES - 1; p++) issue_loads(tid, p, block_m, block_n, sbase);

    // Precomputed intra-warp ldmatrix offsets
    const int a_row = wm * 32 + (lane & 15);            // + mf*16
    const int a_colb = ((lane >> 4) & 1) * 16;          // bytes; + ks*32
    const int b_krow = (lane & 7) + ((lane >> 3) & 1) * 8;  // + ks*16
    const int b_ncol = wn * 64 + ((lane >> 4) & 1) * 8;     // + p*16

#pragma unroll 1
    for (int ch = 0; ch < NCHUNK; ch++) {
        asm volatile("cp.async.wait_group 2;" ::: "memory");
        __syncthreads();

        if (ch + STAGES - 1 < NCHUNK)
            issue_loads(tid, ch + STAGES - 1, block_m, block_n, sbase);
        else
            CP_COMMIT();   // keep group-count invariant

        const uint32_t sb = sbase + (ch & (STAGES - 1)) * STAGE_BYTES;
        const uint32_t aB = sb;
        const uint32_t bB = sb + A_STAGE_BYTES;

#pragma unroll
        for (int ks = 0; ks < 2; ks++) {    // two k16 steps per 32-chunk
            uint32_t a[2][4], b[4][4];
#pragma unroll
            for (int mf = 0; mf < 2; mf++)
                ldsm_x4(a[mf], aB + (a_row + mf * 16) * A_STRIDE + ks * 32 + a_colb);
#pragma unroll
            for (int p = 0; p < 4; p++)
                ldsm_x4_t(b[p], bB + (b_krow + ks * 16) * B_STRIDE
                                   + (b_ncol + p * 16) * 2);
#pragma unroll
            for (int mf = 0; mf < 2; mf++)
#pragma unroll
                for (int nf = 0; nf < 8; nf++)
                    mma16816(c[mf][nf], a[mf],
                             b[nf >> 1][(nf & 1) * 2], b[nf >> 1][(nf & 1) * 2 + 1]);
        }
    }

    // Epilogue: direct float2 stores (each row segment = one 32B sector)
    const int m0 = block_m + wm * 32 + (lane >> 2);
    const int n0 = block_n + wn * 64 + (lane & 3) * 2;
#pragma unroll
    for (int mf = 0; mf < 2; mf++) {
#pragma unroll
        for (int nf = 0; nf < 8; nf++) {
            float* p0 = g_h + (size_t)(m0 + mf * 16) * N_GEMM + n0 + nf * 8;
            *(float2*)p0 = make_float2(c[mf][nf][0], c[mf][nf][1]);
            *(float2*)(p0 + 8 * N_GEMM) = make_float2(c[mf][nf][2], c[mf][nf][3]);
        }
    }
}

// ---------------------------------------------------------------------------
// Scan: syn[b,0]=0 ; syn[b,t] = decay*syn[b,t-1] + h[b,t-1]
// ---------------------------------------------------------------------------
__global__ void __launch_bounds__(256)
scan_kernel(const float* __restrict__ alpha, const float* __restrict__ beta,
            float* __restrict__ out) {
    const int idx = blockIdx.x * blockDim.x + threadIdx.x;
    const int b = idx >> 9;
    const int o = (idx & 511) << 2;

    float4 a4 = *(const float4*)(alpha + o);
    float4 b4 = *(const float4*)(beta + o);
    float4 d = make_float4(a4.x * (1.f - b4.x), a4.y * (1.f - b4.y),
                           a4.z * (1.f - b4.z), a4.w * (1.f - b4.w));

    const float4* hp = (const float4*)(g_h + (size_t)b * TDIM * ODIM + o);
    float4*       op = (float4*)(out + (size_t)b * TDIM * ODIM + o);
    const int s4 = ODIM / 4;

    float4 syn = make_float4(0.f, 0.f, 0.f, 0.f);
    op[0] = syn;
#pragma unroll 4
    for (int t = 1; t < TDIM; t++) {
        float4 h = hp[(size_t)(t - 1) * s4];
        syn.x = fmaf(d.x, syn.x, h.x);
        syn.y = fmaf(d.y, syn.y, h.y);
        syn.z = fmaf(d.z, syn.z, h.z);
        syn.w = fmaf(d.w, syn.w, h.w);
        op[(size_t)t * s4] = syn;
    }
}

// ---------------------------------------------------------------------------
extern "C" void kernel_launch(void* const* d_in, const int* in_sizes, int n_in,
                              void* d_out, int out_size)
{
    const float* x     = (const float*)d_in[0];
    const float* w     = (const float*)d_in[1];
    const float* alpha = (const float*)d_in[2];
    const float* beta  = (const float*)d_in[3];
    float* out         = (float*)d_out;

    cudaFuncSetAttribute(gemm_hmma_kernel,
                         cudaFuncAttributeMaxDynamicSharedMemorySize, SMEM_TOTAL);

    cvt_x_kernel<<<4096, 256>>>(x);
    cvt_w_kernel<<<512, 256>>>(w);

    dim3 grid(N_GEMM / BN, M_GEMM / BM);   // (16, 1000); x-fast => A-panel L2 reuse
    gemm_hmma_kernel<<<grid, 256, SMEM_TOTAL>>>();

    scan_kernel<<<BDIM * (ODIM / 4) / 256, 256>>>(alpha, beta, out);
}